// round 17
// baseline (speedup 1.0000x reference)
#include <cuda_runtime.h>
#include <cuda_bf16.h>

#define SH_C0 0.28209479177387814f
#define SH_C1 0.4886025119029199f

__device__ __constant__ float SH_C2d[5] = {1.0925484305920792f, -1.0925484305920792f, 0.31539156525252005f, -1.0925484305920792f, 0.5462742152960396f};
__device__ __constant__ float SH_C3d[7] = {-0.5900435899266435f, 2.890611442640554f, -0.4570457994644658f, 0.3731763325901154f, -0.4570457994644658f, 1.445305721320277f, -0.5900435899266435f};

// Gang-of-4, fully disjoint gather:
//   lane q loads window float4s {3q, 3q+1, 3q+2}  (12 wide loads per row, 192B, no overlap)
//   lanes 0..2 fetch 3 boundary words from lane q+1 via shfl_down (lane3 self-contained)
//   s-word shift realigns so lane q owns row elements 12q..12q+11 (whole SH coeffs)
//   means: one component per lane (q<3) + shuffle broadcast
//   fdc:   lane q<3 folds SH_C0*d_q into its own color-q partial (butterfly sums it)
//   opac:  lane 3 loads AND stores it; rgb stores one component per lane.
// Window bound: albase+192 <= row_end + 12 - 4s; last row has s=3 -> exact end. Safe.
__global__ void __launch_bounds__(256)
gsh_kernel(const float* __restrict__ means,
           const float* __restrict__ fdc,
           const float* __restrict__ frest,
           const float* __restrict__ opac,
           const float* __restrict__ c2w,
           const int*   __restrict__ mask,
           const int*   __restrict__ step,
           float* __restrict__ out_rgb,
           float* __restrict__ out_opac,
           int M)
{
    const int t = blockIdx.x * blockDim.x + threadIdx.x;
    const int p = t >> 2;
    const int q = t & 3;
    if (p >= M) return;

    const long long idx = (long long)__ldg(mask + p);

    const long long base_bytes = 180ll * idx;
    const long long albase     = base_bytes & ~15ll;
    const int s = (int)((base_bytes - albase) >> 2);     // = idx & 3

    // ---- disjoint wide loads: window words 12q .. 12q+11 ----
    const float4* __restrict__ vp =
        (const float4*)((const char*)frest + albase) + 3 * q;
    const float4 v0 = __ldg(vp + 0);
    const float4 v1 = __ldg(vp + 1);
    const float4 v2 = __ldg(vp + 2);

    // ---- distributed scalar loads ----
    float mval = 0.f, dval = 0.f, op = 0.f;
    if (q < 3) {
        mval = __ldg(means + 3ll * idx + q);
        dval = __ldg(fdc   + 3ll * idx + q);
    } else {
        op = __ldg(opac + idx);
    }

    const float camx = __ldg(c2w + 3);
    const float camy = __ldg(c2w + 7);
    const float camz = __ldg(c2w + 11);
    const int n = min(__ldg(step) / 1000, 3);

    // ---- boundary exchange: words 12q+12..12q+14 live in lane q+1's v0 ----
    const unsigned FULL = 0xffffffffu;
    const float nb0 = __shfl_down_sync(FULL, v0.x, 1);
    const float nb1 = __shfl_down_sync(FULL, v0.y, 1);
    const float nb2 = __shfl_down_sync(FULL, v0.z, 1);

    // ---- 15-word lane window: W[k] == window word 12q+k ----
    float W[15];
    W[0]=v0.x;  W[1]=v0.y;  W[2]=v0.z;  W[3]=v0.w;
    W[4]=v1.x;  W[5]=v1.y;  W[6]=v1.z;  W[7]=v1.w;
    W[8]=v2.x;  W[9]=v2.y;  W[10]=v2.z; W[11]=v2.w;
    W[12]=nb0;  W[13]=nb1;  W[14]=nb2;   // lane3: garbage, never consumed (s<=3 keeps it in 0..11+3)

    // ---- realign by s words: afterwards W[k] == row element 12q+k (k<=11) ----
    if (s & 2) {
#pragma unroll
        for (int k = 0; k < 13; ++k) W[k] = W[k + 2];
    }
    if (s & 1) {
#pragma unroll
        for (int k = 0; k < 12; ++k) W[k] = W[k + 1];
    }

    // ---- means broadcast across the gang ----
    const int lane = threadIdx.x & 31;
    const int g0 = lane & ~3;
    const float mx = __shfl_sync(FULL, mval, g0 + 0);
    const float my = __shfl_sync(FULL, mval, g0 + 1);
    const float mz = __shfl_sync(FULL, mval, g0 + 2);

    const float dx = mx - camx;
    const float dy = my - camy;
    const float dz = mz - camz;
    const float inv = rsqrtf(dx * dx + dy * dy + dz * dz);
    const float x = dx * inv, y = dy * inv, z = dz * inv;
    const float xx = x * x, yy = y * y, zz = z * z;

    float r = 0.f, g = 0.f, b = 0.f;

    if (q == 0) {
        r = SH_C0 * dval;                 // color 0 partial gets dc contribution
        if (n >= 1) {
            const float s1 = -SH_C1 * y;
            const float s2 =  SH_C1 * z;
            const float s3 = -SH_C1 * x;
            r += s1 * W[0] + s2 * W[3] + s3 * W[6];
            g += s1 * W[1] + s2 * W[4] + s3 * W[7];
            b += s1 * W[2] + s2 * W[5] + s3 * W[8];
        }
        if (n >= 2) {
            const float s4 = SH_C2d[0] * (x * y);
            r += s4 * W[9];
            g += s4 * W[10];
            b += s4 * W[11];
        }
    } else if (q == 1) {
        g = SH_C0 * dval;                 // color 1 partial gets dc contribution
        if (n >= 2) {
            const float s5 = SH_C2d[1] * (y * z);
            const float s6 = SH_C2d[2] * (2.0f * zz - xx - yy);
            const float s7 = SH_C2d[3] * (x * z);
            const float s8 = SH_C2d[4] * (xx - yy);
            r += s5 * W[0] + s6 * W[3] + s7 * W[6] + s8 * W[9];
            g += s5 * W[1] + s6 * W[4] + s7 * W[7] + s8 * W[10];
            b += s5 * W[2] + s6 * W[5] + s7 * W[8] + s8 * W[11];
        }
    } else if (q == 2) {
        b = SH_C0 * dval;                 // color 2 partial gets dc contribution
        if (n >= 3) {
            const float s9  = SH_C3d[0] * y * (3.0f * xx - yy);
            const float s10 = SH_C3d[1] * (x * y) * z;
            const float s11 = SH_C3d[2] * y * (4.0f * zz - xx - yy);
            const float s12 = SH_C3d[3] * z * (2.0f * zz - 3.0f * xx - 3.0f * yy);
            r += s9 * W[0] + s10 * W[3] + s11 * W[6] + s12 * W[9];
            g += s9 * W[1] + s10 * W[4] + s11 * W[7] + s12 * W[10];
            b += s9 * W[2] + s10 * W[5] + s11 * W[8] + s12 * W[11];
        }
    } else {
        if (n >= 3) {
            const float s13 = SH_C3d[4] * x * (4.0f * zz - xx - yy);
            const float s14 = SH_C3d[5] * z * (xx - yy);
            const float s15 = SH_C3d[6] * x * (xx - 3.0f * yy);
            r = s13 * W[0] + s14 * W[3] + s15 * W[6];
            g = s13 * W[1] + s14 * W[4] + s15 * W[7];
            b = s13 * W[2] + s14 * W[5] + s15 * W[8];
        }
    }

    // ---- butterfly reduce across the gang ----
    r += __shfl_xor_sync(FULL, r, 1);
    g += __shfl_xor_sync(FULL, g, 1);
    b += __shfl_xor_sync(FULL, b, 1);
    r += __shfl_xor_sync(FULL, r, 2);
    g += __shfl_xor_sync(FULL, g, 2);
    b += __shfl_xor_sync(FULL, b, 2);

    // ---- distributed stores: one 4B store per lane ----
    if (q == 0)      out_rgb[3ll * p + 0] = fmaxf(r + 0.5f, 0.0f);
    else if (q == 1) out_rgb[3ll * p + 1] = fmaxf(g + 0.5f, 0.0f);
    else if (q == 2) out_rgb[3ll * p + 2] = fmaxf(b + 0.5f, 0.0f);
    else             out_opac[p] = op;
}

extern "C" void kernel_launch(void* const* d_in, const int* in_sizes, int n_in,
                              void* d_out, int out_size)
{
    const float* means = (const float*)d_in[0];
    const float* fdc   = (const float*)d_in[1];
    const float* frest = (const float*)d_in[2];
    const float* opac  = (const float*)d_in[3];
    const float* c2w   = (const float*)d_in[4];
    const int*   mask  = (const int*)d_in[5];
    const int*   step  = (const int*)d_in[6];

    int M = in_sizes[5];
    float* out_rgb  = (float*)d_out;
    float* out_opac = (float*)d_out + 3ll * M;

    long long threads_total = 4ll * M;
    int threads = 256;
    int blocks = (int)((threads_total + threads - 1) / threads);
    gsh_kernel<<<blocks, threads>>>(means, fdc, frest, opac, c2w, mask, step,
                                    out_rgb, out_opac, M);
}